// round 13
// baseline (speedup 1.0000x reference)
#include <cuda_runtime.h>
#include <cuda_fp16.h>
#include <cstdint>

#define D 128
#define MAX_NODES 100000

// ---------------------------------------------------------------------------
// Scratch (__device__ globals; no allocation allowed)
// ---------------------------------------------------------------------------
__device__ uint4  g_u4[(size_t)MAX_NODES * 16];   // u[n] = A x[n] + b1 (fp16, 128/row)
__device__ uint4  g_v4[(size_t)MAX_NODES * 16];   // v[n] = B x[n]     (fp16)
__device__ int    g_idx_is64;                     // edge_index dtype flag
// W fragments in exact mma.sync per-lane order:
// index ((ks*32 + ntile)*32 + lane) -> uint4 {b0_hi, b1_hi, b0_lo, b1_lo}
__device__ uint4  g_Wfrag[8 * 32 * 32];           // 128 KB

// ---------------------------------------------------------------------------
// Helpers
// ---------------------------------------------------------------------------
__device__ __forceinline__ uint32_t smem_u32(const void* p) {
    uint32_t a;
    asm("{ .reg .u64 t; cvta.to.shared.u64 t, %1; cvt.u32.u64 %0, t; }" : "=r"(a) : "l"(p));
    return a;
}

__device__ __forceinline__ uint32_t pack_hi_lo(float a, float b, uint32_t& lo_out) {
    __half ha = __float2half_rn(a), hb = __float2half_rn(b);
    float la = a - __half2float(ha), lb = b - __half2float(hb);
    __half2 H = __halves2half2(ha, hb);
    __half2 L = __floats2half2_rn(la, lb);
    lo_out = *reinterpret_cast<uint32_t*>(&L);
    return *reinterpret_cast<uint32_t*>(&H);
}

__device__ __forceinline__ void mma16816(float* c, const uint32_t* a,
                                         uint32_t b0, uint32_t b1) {
    asm volatile(
        "mma.sync.aligned.m16n8k16.row.col.f32.f16.f16.f32 "
        "{%0,%1,%2,%3}, {%4,%5,%6,%7}, {%8,%9}, {%0,%1,%2,%3};"
        : "+f"(c[0]), "+f"(c[1]), "+f"(c[2]), "+f"(c[3])
        : "r"(a[0]), "r"(a[1]), "r"(a[2]), "r"(a[3]), "r"(b0), "r"(b1));
}

#define LDMATRIX_X4(r, addr) \
    asm volatile("ldmatrix.sync.aligned.m8n8.x4.shared.b16 {%0,%1,%2,%3}, [%4];" \
                 : "=r"((r)[0]), "=r"((r)[1]), "=r"((r)[2]), "=r"((r)[3]) \
                 : "r"(addr))

// ---------------------------------------------------------------------------
// Weight prep + index dtype sniff (merged launch).
// B fragments (hi/lo fp16) in mma.sync lane order.
// Logical B[k][n]: n<128 -> W1[n][k] (u), n>=128 -> W1[n-128][128+k] (v).
// Lane: t=lane&3, g=lane>>2; b0={B[ks*16+2t][n],B[..+1][n]}, b1 same at k+8,
// n = ntile*8+g.
// ---------------------------------------------------------------------------
__global__ void prep_kernel(const float* __restrict__ W1,
                            const int* __restrict__ idx32) {
    if (blockIdx.x == 0 && threadIdx.x < 32) {
        int lane = threadIdx.x;
        int nz = (idx32[2 * lane + 1] != 0) ? 1 : 0;
        unsigned m = __ballot_sync(0xffffffffu, nz);
        if (lane == 0) g_idx_is64 = (m == 0);
    }

    int i = blockIdx.x * blockDim.x + threadIdx.x;   // 0..8191
    if (i >= 8 * 32 * 32) return;
    int lane = i & 31;
    int nt   = (i >> 5) & 31;
    int ks   = i >> 10;
    int t = lane & 3, g = lane >> 2;
    int n = nt * 8 + g;
    int k0 = ks * 16 + 2 * t;

    int j    = n & 127;
    int koff = (n >> 7) << 7;   // 0 for u, 128 for v
    float w0 = W1[j * 256 + koff + k0];
    float w1 = W1[j * 256 + koff + k0 + 1];
    float w2 = W1[j * 256 + koff + k0 + 8];
    float w3 = W1[j * 256 + koff + k0 + 9];

    uint32_t l0, l1;
    uint32_t h0 = pack_hi_lo(w0, w1, l0);
    uint32_t h1 = pack_hi_lo(w2, w3, l1);
    g_Wfrag[i] = make_uint4(h0, h1, l0, l1);
}

// ---------------------------------------------------------------------------
// Node GEMM via mma.sync, 2-product split on W only:
//   D = Ah*Bh + Ah*Bl     (x-lo term dropped: ~2.8e-4 rel on h)
// CTA: 128 nodes x 256 outputs; 8 warps as 2(M) x 4(N); warp tile 64x64.
// x tile converted once to fp16 in static smem (272 B row stride,
// conflict-free ldmatrix). b1 folded into u; outputs stored fp16.
// ---------------------------------------------------------------------------
#define XH_STRIDE 136   // halves per row (272 B)

__global__ void __launch_bounds__(256, 1) node_gemm_mma(const float* __restrict__ x,
                                                        const float* __restrict__ b1,
                                                        int n_nodes) {
    __shared__ __align__(16) __half xh[128 * XH_STRIDE];   // 34816 B

    int tid = threadIdx.x;
    int n0  = blockIdx.x * 128;

    // Stage x tile as fp16: 128 rows x 32 float4 = 4096 loads.
    const float4* x4 = reinterpret_cast<const float4*>(x);
    #pragma unroll
    for (int rep = 0; rep < 16; rep++) {
        int tt = tid + rep * 256;      // 0..4095
        int row = tt >> 5, q = tt & 31;
        float4 v = make_float4(0.f, 0.f, 0.f, 0.f);
        if (n0 + row < n_nodes) v = x4[(size_t)(n0 + row) * 32 + q];
        __half2 h01 = __floats2half2_rn(v.x, v.y);
        __half2 h23 = __floats2half2_rn(v.z, v.w);
        int hofs = row * XH_STRIDE + q * 4;     // halves
        *reinterpret_cast<uint2*>(&xh[hofs]) =
            make_uint2(*reinterpret_cast<uint32_t*>(&h01),
                       *reinterpret_cast<uint32_t*>(&h23));
    }
    __syncthreads();

    int lane = tid & 31, wid = tid >> 5;
    int wM = wid >> 2;        // 0..1 : 64-row group
    int wN = wid & 3;         // 0..3 : 64-col group
    int t = lane & 3, g = lane >> 2;

    // ldmatrix lane addressing: lanes 0-15 -> rows (L&15), k-block 0;
    // lanes 16-31 -> same rows, k-block 1 (+8 halves = +16 B).
    int lrow = wM * 64 + (lane & 15);
    int lkb  = lane >> 4;
    uint32_t ph0 = smem_u32(xh) + (uint32_t)(lrow * XH_STRIDE + lkb * 8) * 2;

    float acc[4][8][4];
    #pragma unroll
    for (int mt = 0; mt < 4; mt++)
        #pragma unroll
        for (int j = 0; j < 8; j++)
            #pragma unroll
            for (int q = 0; q < 4; q++) acc[mt][j][q] = 0.f;

    #pragma unroll
    for (int ks = 0; ks < 8; ks++) {
        uint32_t ah[4][4];
        uint32_t ko = ks * 32;                       // 16 halves = 32 B per ks
        #pragma unroll
        for (int mt = 0; mt < 4; mt++)
            LDMATRIX_X4(ah[mt], ph0 + ko + (uint32_t)(mt * 16 * XH_STRIDE * 2));
        #pragma unroll
        for (int j = 0; j < 8; j++) {
            uint4 f = __ldg(&g_Wfrag[((ks * 32 + wN * 8 + j) << 5) + lane]);
            #pragma unroll
            for (int mt = 0; mt < 4; mt++) {
                mma16816(acc[mt][j], ah[mt], f.x, f.y);   // Ah*Bh
                mma16816(acc[mt][j], ah[mt], f.z, f.w);   // Ah*Bl
            }
        }
    }

    // Epilogue: cols wN*64 + j*8 + 2t. wN<2 -> u (+ b1 fold), wN>=2 -> v.
    __half* dstbase = reinterpret_cast<__half*>((wN < 2) ? g_u4 : g_v4);
    int colbase = (wN < 2) ? wN * 64 : (wN - 2) * 64;
    #pragma unroll
    for (int mt = 0; mt < 4; mt++) {
        int node0 = n0 + wM * 64 + mt * 16 + g;
        int node1 = node0 + 8;
        #pragma unroll
        for (int j = 0; j < 8; j++) {
            int col = colbase + j * 8 + 2 * t;
            float bb0 = 0.f, bb1 = 0.f;
            if (wN < 2) { float2 bv = *reinterpret_cast<const float2*>(&b1[col]);
                          bb0 = bv.x; bb1 = bv.y; }
            if (node0 < n_nodes)
                *reinterpret_cast<__half2*>(&dstbase[(size_t)node0 * D + col]) =
                    __floats2half2_rn(acc[mt][j][0] + bb0, acc[mt][j][1] + bb1);
            if (node1 < n_nodes)
                *reinterpret_cast<__half2*>(&dstbase[(size_t)node1 * D + col]) =
                    __floats2half2_rn(acc[mt][j][2] + bb0, acc[mt][j][3] + bb1);
        }
    }
}

// ---------------------------------------------------------------------------
// Edge phase: 8 lanes per edge, 8 edges per warp iteration (each lane carries
// 2 edges: e0+sub and e0+sub+4). All index loads then all gathers issued
// before compute -> 8 independent load chains per lane in flight.
// Lane: sub = lane>>3, fl = lane&7 (features [fl*16, fl*16+16)).
// out[e] = sum_j relu(u'[s][j] + v[d][j]) * w2[j] + b2   (b1 already in u')
// ---------------------------------------------------------------------------
__device__ __forceinline__ float dot16h(uint4 uu, uint4 vv, const __half2* w2h) {
    const __half2* up = reinterpret_cast<const __half2*>(&uu);
    const __half2* vp = reinterpret_cast<const __half2*>(&vv);
    __half2 zero = __float2half2_rn(0.f);
    __half2 p0 = __hmul2(__hmax2(__hadd2(up[0], vp[0]), zero), w2h[0]);
    __half2 p1 = __hmul2(__hmax2(__hadd2(up[1], vp[1]), zero), w2h[1]);
    __half2 p2 = __hmul2(__hmax2(__hadd2(up[2], vp[2]), zero), w2h[2]);
    __half2 p3 = __hmul2(__hmax2(__hadd2(up[3], vp[3]), zero), w2h[3]);
    __half2 q0 = __hadd2(p0, p1);
    __half2 q1 = __hadd2(p2, p3);
    float2 f0 = __half22float2(q0);
    float2 f1 = __half22float2(q1);
    return (f0.x + f0.y) + (f1.x + f1.y);
}

__global__ void __launch_bounds__(128) edge_kernel(const int* __restrict__ idx32,
                                                   const float* __restrict__ W2,
                                                   const float* __restrict__ b2,
                                                   float* __restrict__ out,
                                                   int E) {
    int lane   = threadIdx.x & 31;
    int sub    = lane >> 3;        // edge slot within group
    int fl     = lane & 7;         // feature-lane
    int warp   = (int)((blockIdx.x * blockDim.x + threadIdx.x) >> 5);
    int nwarps = (int)((gridDim.x * blockDim.x) >> 5);

    int is64 = g_idx_is64;
    int mul  = is64 ? 2 : 1;
    int dofs = is64 ? 2 * E : E;

    // w2 for this lane's 16 features, as 8 half2 regs.
    __half2 w2h[8];
    #pragma unroll
    for (int q = 0; q < 4; q++) {
        float4 wv = reinterpret_cast<const float4*>(W2)[fl * 4 + q];
        w2h[2 * q + 0] = __floats2half2_rn(wv.x, wv.y);
        w2h[2 * q + 1] = __floats2half2_rn(wv.z, wv.w);
    }
    float b2s = __ldg(b2);

    int G = E >> 3;   // groups of 8 edges
    for (int gi = warp; gi < G; gi += nwarps) {
        int ea = (gi << 3) + sub;        // edge A
        int eb = ea + 4;                 // edge B
        // indices first (independent chains)
        int sa = __ldg(&idx32[ea * mul]);
        int da = __ldg(&idx32[dofs + ea * mul]);
        int sb = __ldg(&idx32[eb * mul]);
        int db = __ldg(&idx32[dofs + eb * mul]);

        // all gathers issued back-to-back: 8 x 16B chains per lane
        const uint4* Ua = g_u4 + (size_t)sa * 16 + fl * 2;
        const uint4* Va = g_v4 + (size_t)da * 16 + fl * 2;
        const uint4* Ub = g_u4 + (size_t)sb * 16 + fl * 2;
        const uint4* Vb = g_v4 + (size_t)db * 16 + fl * 2;
        uint4 ua0 = __ldg(Ua), ua1 = __ldg(Ua + 1);
        uint4 va0 = __ldg(Va), va1 = __ldg(Va + 1);
        uint4 ub0 = __ldg(Ub), ub1 = __ldg(Ub + 1);
        uint4 vb0 = __ldg(Vb), vb1 = __ldg(Vb + 1);

        float ra = dot16h(ua0, va0, w2h) + dot16h(ua1, va1, w2h + 4);
        float rb = dot16h(ub0, vb0, w2h) + dot16h(ub1, vb1, w2h + 4);

        ra += __shfl_xor_sync(0xffffffffu, ra, 4);
        rb += __shfl_xor_sync(0xffffffffu, rb, 4);
        ra += __shfl_xor_sync(0xffffffffu, ra, 2);
        rb += __shfl_xor_sync(0xffffffffu, rb, 2);
        ra += __shfl_xor_sync(0xffffffffu, ra, 1);
        rb += __shfl_xor_sync(0xffffffffu, rb, 1);

        if (fl == 0) {
            out[ea] = ra + b2s;   // lanes 0,8,16,24 -> coalesced 16 B
            out[eb] = rb + b2s;
        }
    }

    // tail (E % 8 edges), handled by warp 0: up to 2 edges per sub slot.
    int base = E & ~7;
    int rem  = E - base;
    if (warp == 0 && rem) {
        #pragma unroll
        for (int pass = 0; pass < 2; pass++) {
            int e = base + sub + pass * 4;
            if (e < E) {
                int s = __ldg(&idx32[e * mul]);
                int d = __ldg(&idx32[dofs + e * mul]);
                const uint4* Ur = g_u4 + (size_t)s * 16 + fl * 2;
                const uint4* Vr = g_v4 + (size_t)d * 16 + fl * 2;
                uint4 u0 = __ldg(Ur), u1 = __ldg(Ur + 1);
                uint4 v0 = __ldg(Vr), v1 = __ldg(Vr + 1);
                float r = dot16h(u0, v0, w2h) + dot16h(u1, v1, w2h + 4);
                r += __shfl_xor_sync(0xffffffffu, r, 4);
                r += __shfl_xor_sync(0xffffffffu, r, 2);
                r += __shfl_xor_sync(0xffffffffu, r, 1);
                if (fl == 0) out[e] = r + b2s;
            }
        }
    }
}

// ---------------------------------------------------------------------------
// Inputs: x [100000,128] f32, edge_index [2,E] (int32/int64 sniffed),
// W1 [128,256] f32, b1 [128] f32, W2 [1,128] f32, b2 [1] f32. Output: [E] f32.
// ---------------------------------------------------------------------------
extern "C" void kernel_launch(void* const* d_in, const int* in_sizes, int n_in,
                              void* d_out, int out_size) {
    const float* x    = (const float*)d_in[0];
    const int*   ei32 = (const int*)d_in[1];
    const float* W1   = (const float*)d_in[2];
    const float* b1   = (const float*)d_in[3];
    const float* W2   = (const float*)d_in[4];
    const float* b2   = (const float*)d_in[5];
    float* out = (float*)d_out;

    int n_nodes = in_sizes[0] / D;
    int E       = in_sizes[1] / 2;

    prep_kernel<<<32, 256>>>(W1, ei32);
    node_gemm_mma<<<(n_nodes + 127) / 128, 256>>>(x, b1, n_nodes);
    edge_kernel<<<2368, 128>>>(ei32, W2, b2, out, E);   // 148 SMs x 16 blocks
}

// round 15
// speedup vs baseline: 1.1217x; 1.1217x over previous
#include <cuda_runtime.h>
#include <cuda_fp16.h>
#include <cstdint>

#define D 128
#define MAX_NODES 100000

// ---------------------------------------------------------------------------
// Scratch (__device__ globals; no allocation allowed)
// ---------------------------------------------------------------------------
__device__ uint4  g_u4[(size_t)MAX_NODES * 16];   // u[n] = A x[n] + b1 (fp16, 128/row)
__device__ uint4  g_v4[(size_t)MAX_NODES * 16];   // v[n] = B x[n]     (fp16)
__device__ int    g_idx_is64;                     // edge_index dtype flag
// W fragments in exact mma.sync per-lane order:
// index ((ks*32 + ntile)*32 + lane) -> uint4 {b0_hi, b1_hi, b0_lo, b1_lo}
__device__ uint4  g_Wfrag[8 * 32 * 32];           // 128 KB

// ---------------------------------------------------------------------------
// Helpers
// ---------------------------------------------------------------------------
__device__ __forceinline__ uint32_t smem_u32(const void* p) {
    uint32_t a;
    asm("{ .reg .u64 t; cvta.to.shared.u64 t, %1; cvt.u32.u64 %0, t; }" : "=r"(a) : "l"(p));
    return a;
}

__device__ __forceinline__ uint32_t pack_hi_lo(float a, float b, uint32_t& lo_out) {
    __half ha = __float2half_rn(a), hb = __float2half_rn(b);
    float la = a - __half2float(ha), lb = b - __half2float(hb);
    __half2 H = __halves2half2(ha, hb);
    __half2 L = __floats2half2_rn(la, lb);
    lo_out = *reinterpret_cast<uint32_t*>(&L);
    return *reinterpret_cast<uint32_t*>(&H);
}

__device__ __forceinline__ void mma16816(float* c, const uint32_t* a,
                                         uint32_t b0, uint32_t b1) {
    asm volatile(
        "mma.sync.aligned.m16n8k16.row.col.f32.f16.f16.f32 "
        "{%0,%1,%2,%3}, {%4,%5,%6,%7}, {%8,%9}, {%0,%1,%2,%3};"
        : "+f"(c[0]), "+f"(c[1]), "+f"(c[2]), "+f"(c[3])
        : "r"(a[0]), "r"(a[1]), "r"(a[2]), "r"(a[3]), "r"(b0), "r"(b1));
}

#define LDMATRIX_X4(r, addr) \
    asm volatile("ldmatrix.sync.aligned.m8n8.x4.shared.b16 {%0,%1,%2,%3}, [%4];" \
                 : "=r"((r)[0]), "=r"((r)[1]), "=r"((r)[2]), "=r"((r)[3]) \
                 : "r"(addr))

// ---------------------------------------------------------------------------
// Weight prep + index dtype sniff (merged launch).
// B fragments (hi/lo fp16) in mma.sync lane order.
// Logical B[k][n]: n<128 -> W1[n][k] (u), n>=128 -> W1[n-128][128+k] (v).
// Lane: t=lane&3, g=lane>>2; b0={B[ks*16+2t][n],B[..+1][n]}, b1 same at k+8,
// n = ntile*8+g.
// ---------------------------------------------------------------------------
__global__ void prep_kernel(const float* __restrict__ W1,
                            const int* __restrict__ idx32) {
    if (blockIdx.x == 0 && threadIdx.x < 32) {
        int lane = threadIdx.x;
        int nz = (idx32[2 * lane + 1] != 0) ? 1 : 0;
        unsigned m = __ballot_sync(0xffffffffu, nz);
        if (lane == 0) g_idx_is64 = (m == 0);
    }

    int i = blockIdx.x * blockDim.x + threadIdx.x;   // 0..8191
    if (i >= 8 * 32 * 32) return;
    int lane = i & 31;
    int nt   = (i >> 5) & 31;
    int ks   = i >> 10;
    int t = lane & 3, g = lane >> 2;
    int n = nt * 8 + g;
    int k0 = ks * 16 + 2 * t;

    int j    = n & 127;
    int koff = (n >> 7) << 7;   // 0 for u, 128 for v
    float w0 = W1[j * 256 + koff + k0];
    float w1 = W1[j * 256 + koff + k0 + 1];
    float w2 = W1[j * 256 + koff + k0 + 8];
    float w3 = W1[j * 256 + koff + k0 + 9];

    uint32_t l0, l1;
    uint32_t h0 = pack_hi_lo(w0, w1, l0);
    uint32_t h1 = pack_hi_lo(w2, w3, l1);
    g_Wfrag[i] = make_uint4(h0, h1, l0, l1);
}

// ---------------------------------------------------------------------------
// Node GEMM via mma.sync, 2-product split on W only:
//   D = Ah*Bh + Ah*Bl     (x-lo term dropped: ~2.8e-4 rel on h)
// Grid: 2 * ceil(n/128) CTAs; half = blockIdx.x & 1 (0 -> u cols, 1 -> v cols)
// so the u/v CTA pair for a node range runs adjacently and shares the x tile
// via L2. CTA: 128 nodes x 128 outputs; 8 warps as 2(M) x 4(N); warp tile
// 64x32 -> acc = 64 regs -> 2 CTAs/SM for latency hiding.
// x tile converted once to fp16 in static smem (272 B row stride,
// conflict-free ldmatrix). b1 folded into u; outputs stored fp16.
// ---------------------------------------------------------------------------
#define XH_STRIDE 136   // halves per row (272 B)

__global__ void __launch_bounds__(256, 2) node_gemm_mma(const float* __restrict__ x,
                                                        const float* __restrict__ b1,
                                                        int n_nodes) {
    __shared__ __align__(16) __half xh[128 * XH_STRIDE];   // 34816 B

    int tid  = threadIdx.x;
    int half = blockIdx.x & 1;                 // 0 = u, 1 = v
    int n0   = (blockIdx.x >> 1) * 128;

    // Stage x tile as fp16: 128 rows x 32 float4 = 4096 loads.
    const float4* x4 = reinterpret_cast<const float4*>(x);
    #pragma unroll
    for (int rep = 0; rep < 16; rep++) {
        int tt = tid + rep * 256;      // 0..4095
        int row = tt >> 5, q = tt & 31;
        float4 v = make_float4(0.f, 0.f, 0.f, 0.f);
        if (n0 + row < n_nodes) v = x4[(size_t)(n0 + row) * 32 + q];
        __half2 h01 = __floats2half2_rn(v.x, v.y);
        __half2 h23 = __floats2half2_rn(v.z, v.w);
        int hofs = row * XH_STRIDE + q * 4;     // halves
        *reinterpret_cast<uint2*>(&xh[hofs]) =
            make_uint2(*reinterpret_cast<uint32_t*>(&h01),
                       *reinterpret_cast<uint32_t*>(&h23));
    }
    __syncthreads();

    int lane = tid & 31, wid = tid >> 5;
    int wM = wid >> 2;        // 0..1 : 64-row group
    int wN = wid & 3;         // 0..3 : 32-col group within the 128-col half
    int t = lane & 3, g = lane >> 2;

    // ldmatrix lane addressing: lanes 0-15 -> rows (L&15), k-block 0;
    // lanes 16-31 -> same rows, k-block 1 (+8 halves = +16 B).
    int lrow = wM * 64 + (lane & 15);
    int lkb  = lane >> 4;
    uint32_t ph0 = smem_u32(xh) + (uint32_t)(lrow * XH_STRIDE + lkb * 8) * 2;

    float acc[4][4][4];
    #pragma unroll
    for (int mt = 0; mt < 4; mt++)
        #pragma unroll
        for (int j = 0; j < 4; j++)
            #pragma unroll
            for (int q = 0; q < 4; q++) acc[mt][j][q] = 0.f;

    int ntbase = half * 16 + wN * 4;   // global ntile base for this warp

    #pragma unroll
    for (int ks = 0; ks < 8; ks++) {
        uint32_t ah[4][4];
        uint32_t ko = ks * 32;                       // 16 halves = 32 B per ks
        #pragma unroll
        for (int mt = 0; mt < 4; mt++)
            LDMATRIX_X4(ah[mt], ph0 + ko + (uint32_t)(mt * 16 * XH_STRIDE * 2));
        #pragma unroll
        for (int j = 0; j < 4; j++) {
            uint4 f = __ldg(&g_Wfrag[((ks * 32 + ntbase + j) << 5) + lane]);
            #pragma unroll
            for (int mt = 0; mt < 4; mt++) {
                mma16816(acc[mt][j], ah[mt], f.x, f.y);   // Ah*Bh
                mma16816(acc[mt][j], ah[mt], f.z, f.w);   // Ah*Bl
            }
        }
    }

    // Epilogue: cols wN*32 + j*8 + 2t within the half. half==0 -> u (+ b1).
    __half* dstbase = reinterpret_cast<__half*>(half ? g_v4 : g_u4);
    #pragma unroll
    for (int mt = 0; mt < 4; mt++) {
        int node0 = n0 + wM * 64 + mt * 16 + g;
        int node1 = node0 + 8;
        #pragma unroll
        for (int j = 0; j < 4; j++) {
            int col = wN * 32 + j * 8 + 2 * t;
            float bb0 = 0.f, bb1 = 0.f;
            if (half == 0) { float2 bv = *reinterpret_cast<const float2*>(&b1[col]);
                             bb0 = bv.x; bb1 = bv.y; }
            if (node0 < n_nodes)
                *reinterpret_cast<__half2*>(&dstbase[(size_t)node0 * D + col]) =
                    __floats2half2_rn(acc[mt][j][0] + bb0, acc[mt][j][1] + bb1);
            if (node1 < n_nodes)
                *reinterpret_cast<__half2*>(&dstbase[(size_t)node1 * D + col]) =
                    __floats2half2_rn(acc[mt][j][2] + bb0, acc[mt][j][3] + bb1);
        }
    }
}

// ---------------------------------------------------------------------------
// Edge phase (R12 config — proven): 8 lanes per edge, 4 edges per warp
// iteration. Lane: sub = lane>>3 (edge), fl = lane&7 (features [fl*16,+16)).
// fp16 add+relu+mul (w2 in fp16, 8 half2 regs), one fp16 pairwise add level,
// then cvt + fp32 tree; 3-stage shuffle reduce within 8 lanes.
// out[e] = sum_j relu(u'[s][j] + v[d][j]) * w2[j] + b2   (b1 already in u')
// ---------------------------------------------------------------------------
__device__ __forceinline__ float dot16h(uint4 uu, uint4 vv, const __half2* w2h) {
    const __half2* up = reinterpret_cast<const __half2*>(&uu);
    const __half2* vp = reinterpret_cast<const __half2*>(&vv);
    __half2 zero = __float2half2_rn(0.f);
    __half2 p0 = __hmul2(__hmax2(__hadd2(up[0], vp[0]), zero), w2h[0]);
    __half2 p1 = __hmul2(__hmax2(__hadd2(up[1], vp[1]), zero), w2h[1]);
    __half2 p2 = __hmul2(__hmax2(__hadd2(up[2], vp[2]), zero), w2h[2]);
    __half2 p3 = __hmul2(__hmax2(__hadd2(up[3], vp[3]), zero), w2h[3]);
    __half2 q0 = __hadd2(p0, p1);
    __half2 q1 = __hadd2(p2, p3);
    float2 f0 = __half22float2(q0);
    float2 f1 = __half22float2(q1);
    return (f0.x + f0.y) + (f1.x + f1.y);
}

__global__ void __launch_bounds__(128) edge_kernel(const int* __restrict__ idx32,
                                                   const float* __restrict__ W2,
                                                   const float* __restrict__ b2,
                                                   float* __restrict__ out,
                                                   int E) {
    int lane   = threadIdx.x & 31;
    int sub    = lane >> 3;        // edge within group
    int fl     = lane & 7;         // feature-lane
    int warp   = (int)((blockIdx.x * blockDim.x + threadIdx.x) >> 5);
    int nwarps = (int)((gridDim.x * blockDim.x) >> 5);

    int is64 = g_idx_is64;
    int mul  = is64 ? 2 : 1;
    int dofs = is64 ? 2 * E : E;

    // w2 for this lane's 16 features, as 8 half2 regs.
    __half2 w2h[8];
    #pragma unroll
    for (int q = 0; q < 4; q++) {
        float4 wv = reinterpret_cast<const float4*>(W2)[fl * 4 + q];
        w2h[2 * q + 0] = __floats2half2_rn(wv.x, wv.y);
        w2h[2 * q + 1] = __floats2half2_rn(wv.z, wv.w);
    }
    float b2s = __ldg(b2);

    int G = E >> 2;
    for (int gi = warp; gi < G; gi += nwarps) {
        int e = (gi << 2) + sub;
        int s = __ldg(&idx32[e * mul]);
        int d = __ldg(&idx32[dofs + e * mul]);

        const uint4* Ur = g_u4 + (size_t)s * 16 + fl * 2;
        const uint4* Vr = g_v4 + (size_t)d * 16 + fl * 2;
        uint4 u0 = __ldg(Ur), u1 = __ldg(Ur + 1);
        uint4 v0 = __ldg(Vr), v1 = __ldg(Vr + 1);

        float r = dot16h(u0, v0, w2h) + dot16h(u1, v1, w2h + 4);

        r += __shfl_xor_sync(0xffffffffu, r, 4);
        r += __shfl_xor_sync(0xffffffffu, r, 2);
        r += __shfl_xor_sync(0xffffffffu, r, 1);

        if (fl == 0) out[e] = r + b2s;   // 4 lanes -> coalesced 16 B
    }

    // tail (E % 4 edges), handled by warp 0
    int rem = E & 3;
    if (warp == 0 && sub < rem) {
        int e = (E & ~3) + sub;
        int s = __ldg(&idx32[e * mul]);
        int d = __ldg(&idx32[dofs + e * mul]);
        const uint4* Ur = g_u4 + (size_t)s * 16 + fl * 2;
        const uint4* Vr = g_v4 + (size_t)d * 16 + fl * 2;
        uint4 u0 = __ldg(Ur), u1 = __ldg(Ur + 1);
        uint4 v0 = __ldg(Vr), v1 = __ldg(Vr + 1);
        float r = dot16h(u0, v0, w2h) + dot16h(u1, v1, w2h + 4);
        r += __shfl_xor_sync(0xffffffffu, r, 4);
        r += __shfl_xor_sync(0xffffffffu, r, 2);
        r += __shfl_xor_sync(0xffffffffu, r, 1);
        if (fl == 0) out[e] = r + b2s;
    }
}

// ---------------------------------------------------------------------------
// Inputs: x [100000,128] f32, edge_index [2,E] (int32/int64 sniffed),
// W1 [128,256] f32, b1 [128] f32, W2 [1,128] f32, b2 [1] f32. Output: [E] f32.
// ---------------------------------------------------------------------------
extern "C" void kernel_launch(void* const* d_in, const int* in_sizes, int n_in,
                              void* d_out, int out_size) {
    const float* x    = (const float*)d_in[0];
    const int*   ei32 = (const int*)d_in[1];
    const float* W1   = (const float*)d_in[2];
    const float* b1   = (const float*)d_in[3];
    const float* W2   = (const float*)d_in[4];
    const float* b2   = (const float*)d_in[5];
    float* out = (float*)d_out;

    int n_nodes = in_sizes[0] / D;
    int E       = in_sizes[1] / 2;

    prep_kernel<<<32, 256>>>(W1, ei32);
    node_gemm_mma<<<2 * ((n_nodes + 127) / 128), 256>>>(x, b1, n_nodes);
    edge_kernel<<<4096, 128>>>(ei32, W2, b2, out, E);
}